// round 8
// baseline (speedup 1.0000x reference)
#include <cuda_runtime.h>
#include <cuda_bf16.h>
#include <cuda_fp16.h>
#include <cstdint>

#define NROWS 8192
#define DIM   1024
#define DIMB  1024                         // bytes per row (fp8)
#define SCALE_T 14.4269504088896341f       // (1/T)*log2(e)
#define FP8_SCALE 32.0f
#define EPI_SCALE (SCALE_T / (FP8_SCALE * FP8_SCALE))   // applied to raw acc
#define LN2F 0.69314718055994531f

// ---------------- scratch ----------------
__device__ uint8_t g_im8[(size_t)NROWS * DIM];    // e4m3, normalized * 32
__device__ uint8_t g_cap8[(size_t)NROWS * DIM];   // e4m3, normalized * 32
__device__ float g_rowsum[NROWS];
__device__ float g_colsum[NROWS];
__device__ float g_diag[NROWS];                   // t_ii (exp2-domain logits)
__device__ float g_parta[32];
__device__ float g_partd[32];

// ---------------- helpers ----------------
__device__ __forceinline__ uint32_t smem_u32(const void* p) {
    uint32_t a;
    asm("{ .reg .u64 t; cvta.to.shared.u64 t, %1; cvt.u32.u64 %0, t; }" : "=r"(a) : "l"(p));
    return a;
}
__device__ __forceinline__ uint64_t gmem_u64(const void* p) {
    uint64_t a;
    asm("cvta.to.global.u64 %0, %1;" : "=l"(a) : "l"(p));
    return a;
}
__device__ __forceinline__ __half2 u2h(uint32_t x) { __half2 h; *reinterpret_cast<uint32_t*>(&h) = x; return h; }
#define SW128(o) ((o) ^ (((o) >> 3) & 0x70))

// ---------------- 1) normalize -> e4m3 * 32 ----------------
__global__ void normalize_kernel(const float* __restrict__ im,
                                 const float* __restrict__ cap) {
    int row = blockIdx.x;
    const float* src = (blockIdx.y == 0) ? im : cap;
    uint8_t* dst = (blockIdx.y == 0) ? g_im8 : g_cap8;

    const float4* src4 = reinterpret_cast<const float4*>(src + (size_t)row * DIM);
    float4 v = src4[threadIdx.x];
    float ss = v.x * v.x + v.y * v.y + v.z * v.z + v.w * v.w;
    #pragma unroll
    for (int o = 16; o; o >>= 1) ss += __shfl_xor_sync(0xffffffffu, ss, o);
    __shared__ float wss[8];
    if ((threadIdx.x & 31) == 0) wss[threadIdx.x >> 5] = ss;
    __syncthreads();
    float total = 0.f;
    #pragma unroll
    for (int i = 0; i < 8; i++) total += wss[i];

    float inv = rsqrtf(total) * FP8_SCALE;
    uint16_t p01, p23;
    asm("cvt.rn.satfinite.e4m3x2.f32 %0, %1, %2;" : "=h"(p01) : "f"(v.y * inv), "f"(v.x * inv));
    asm("cvt.rn.satfinite.e4m3x2.f32 %0, %1, %2;" : "=h"(p23) : "f"(v.w * inv), "f"(v.z * inv));
    uint32_t* d32 = reinterpret_cast<uint32_t*>(dst + (size_t)row * DIMB);
    d32[threadIdx.x] = (uint32_t)p01 | ((uint32_t)p23 << 16);
}

// ---------------- 2) zero ----------------
__global__ void zero_kernel() {
    int i = blockIdx.x * blockDim.x + threadIdx.x;
    if (i < NROWS) { g_rowsum[i] = 0.f; g_colsum[i] = 0.f; }
}

// ---------------- 3) diag from the SAME fp8 data ----------------
__device__ __forceinline__ float dot16_e4m3(uint4 a, uint4 b) {
    const uint16_t* pa = reinterpret_cast<const uint16_t*>(&a);
    const uint16_t* pb = reinterpret_cast<const uint16_t*>(&b);
    float s = 0.f;
    #pragma unroll
    for (int i = 0; i < 8; i++) {
        uint32_t ha, hb;
        asm("cvt.rn.f16x2.e4m3x2 %0, %1;" : "=r"(ha) : "h"(pa[i]));
        asm("cvt.rn.f16x2.e4m3x2 %0, %1;" : "=r"(hb) : "h"(pb[i]));
        float2 fa = __half22float2(u2h(ha));
        float2 fb = __half22float2(u2h(hb));
        s += fa.x * fb.x + fa.y * fb.y;
    }
    return s;
}

__global__ void diag_kernel() {
    int wid = threadIdx.x >> 5, lane = threadIdx.x & 31;
    int row = blockIdx.x * 8 + wid;
    const uint4* A = reinterpret_cast<const uint4*>(g_im8 + (size_t)row * DIMB);
    const uint4* B = reinterpret_cast<const uint4*>(g_cap8 + (size_t)row * DIMB);
    float acc = 0.f;
    #pragma unroll
    for (int q = 0; q < 2; q++)
        acc += dot16_e4m3(A[lane + 32 * q], B[lane + 32 * q]);
    #pragma unroll
    for (int o = 16; o; o >>= 1) acc += __shfl_xor_sync(0xffffffffu, acc, o);
    if (lane == 0) g_diag[row] = acc * EPI_SCALE;
}

// ---------------- 4) fp8 mma.sync GEMM + exp2 + register reduce ----------------
// CTA tile 128x128, BK=128 fp8 (128B rows), 3-stage cp.async, 8 warps = 2(M)x4(N).
#define BM 128
#define BN 128
#define STAGE_BYTES 32768                  // A 16KB + B 16KB
#define DYN_BYTES (3 * STAGE_BYTES + 1024)

extern __shared__ char dynsmem[];

__device__ __forceinline__ void issue_tile(uint32_t sStage, uint64_t gA, uint64_t gB,
                                           int c, int tid) {
    const uint32_t k0b = (uint32_t)c * 128;          // 128 B per K-chunk
    #pragma unroll
    for (int q = 0; q < 4; q++) {
        int chunk = tid + q * 256;
        int row = chunk >> 3, kc = chunk & 7;
        uint32_t soff = SW128(row * 128 + kc * 16);
        uint64_t goff = (uint64_t)row * DIMB + k0b + kc * 16;
        asm volatile("cp.async.cg.shared.global [%0], [%1], 16;"
                     :: "r"(sStage + soff), "l"(gA + goff) : "memory");
        asm volatile("cp.async.cg.shared.global [%0], [%1], 16;"
                     :: "r"(sStage + 16384 + soff), "l"(gB + goff) : "memory");
    }
}

__global__ void __launch_bounds__(256, 2) gemm_kernel() {
    const int tid = threadIdx.x, wid = tid >> 5, lane = tid & 31;
    const int warpM = wid >> 2;            // 0..1 -> 64-row slab
    const int warpN = wid & 3;             // 0..3 -> 32-col slab
    const int rowBase = blockIdx.y * BM;
    const int colBase = blockIdx.x * BN;

    __shared__ float rowsum_s[BM];
    __shared__ float colsum_s[BN];
    if (tid < BM) { rowsum_s[tid] = 0.f; colsum_s[tid] = 0.f; }

    uint32_t raw = smem_u32(dynsmem);
    uint32_t sbase = (raw + 1023u) & ~1023u;

    const uint64_t gA = gmem_u64(&g_im8[(size_t)rowBase * DIMB]);
    const uint64_t gB = gmem_u64(&g_cap8[(size_t)colBase * DIMB]);

    issue_tile(sbase + 0 * STAGE_BYTES, gA, gB, 0, tid);
    asm volatile("cp.async.commit_group;" ::: "memory");
    issue_tile(sbase + 1 * STAGE_BYTES, gA, gB, 1, tid);
    asm volatile("cp.async.commit_group;" ::: "memory");

    float acc[4][4][4];
    #pragma unroll
    for (int i = 0; i < 4; i++)
        #pragma unroll
        for (int j = 0; j < 4; j++)
            #pragma unroll
            for (int r = 0; r < 4; r++) acc[i][j][r] = 0.f;

    // ldmatrix lane geometry (byte-identical to bf16-k16 case)
    const int laneRow = lane & 15;
    const uint32_t aXor = (uint32_t)((laneRow & 7) << 4);
    const uint32_t aHi  = (uint32_t)((lane >> 4) * 16);
    const int rowB0 = ((lane >> 4) & 1) * 8 + (lane & 7);
    const uint32_t bXor = (uint32_t)((lane & 7) << 4);
    const uint32_t bHi  = (uint32_t)(((lane >> 3) & 1) * 16);

    for (int c = 0; c < 8; c++) {
        asm volatile("cp.async.wait_group 1;" ::: "memory");
        __syncthreads();
        if (c + 2 < 8)
            issue_tile(sbase + ((c + 2) % 3) * STAGE_BYTES, gA, gB, c + 2, tid);
        asm volatile("cp.async.commit_group;" ::: "memory");

        const uint32_t sA = sbase + (c % 3) * STAGE_BYTES;
        const uint32_t sB = sA + 16384;

        #pragma unroll
        for (int kk = 0; kk < 4; kk++) {            // 4 x k32 per 128B chunk
            uint32_t a[4][4], b[2][4];
            #pragma unroll
            for (int i = 0; i < 4; i++) {
                uint32_t addr = sA + (uint32_t)(warpM * 64 + i * 16 + laneRow) * 128
                              + (((uint32_t)kk * 32 + aHi) ^ aXor);
                asm volatile("ldmatrix.sync.aligned.m8n8.x4.shared.b16 {%0,%1,%2,%3}, [%4];"
                             : "=r"(a[i][0]), "=r"(a[i][1]), "=r"(a[i][2]), "=r"(a[i][3])
                             : "r"(addr));
            }
            #pragma unroll
            for (int jb = 0; jb < 2; jb++) {
                uint32_t addr = sB + (uint32_t)(warpN * 32 + jb * 16 + rowB0) * 128
                              + (((uint32_t)kk * 32 + bHi) ^ bXor);
                asm volatile("ldmatrix.sync.aligned.m8n8.x4.shared.b16 {%0,%1,%2,%3}, [%4];"
                             : "=r"(b[jb][0]), "=r"(b[jb][1]), "=r"(b[jb][2]), "=r"(b[jb][3])
                             : "r"(addr));
            }
            #pragma unroll
            for (int i = 0; i < 4; i++) {
                #pragma unroll
                for (int j = 0; j < 4; j++) {
                    uint32_t b0 = b[j >> 1][(j & 1) * 2];
                    uint32_t b1 = b[j >> 1][(j & 1) * 2 + 1];
                    asm volatile(
                        "mma.sync.aligned.m16n8k32.row.col.f32.e4m3.e4m3.f32 "
                        "{%0,%1,%2,%3}, {%4,%5,%6,%7}, {%8,%9}, {%0,%1,%2,%3};"
                        : "+f"(acc[i][j][0]), "+f"(acc[i][j][1]),
                          "+f"(acc[i][j][2]), "+f"(acc[i][j][3])
                        : "r"(a[i][0]), "r"(a[i][1]), "r"(a[i][2]), "r"(a[i][3]),
                          "r"(b0), "r"(b1));
                }
            }
        }
    }

    // ---- epilogue: scale + exp2 in place, register reductions ----
    #pragma unroll
    for (int i = 0; i < 4; i++)
        #pragma unroll
        for (int j = 0; j < 4; j++)
            #pragma unroll
            for (int r = 0; r < 4; r++) {
                float t = acc[i][j][r] * EPI_SCALE;
                asm("ex2.approx.f32 %0, %0;" : "+f"(t));
                acc[i][j][r] = t;
            }

    #pragma unroll
    for (int i = 0; i < 4; i++) {
        float r0 = 0.f, r1 = 0.f;
        #pragma unroll
        for (int j = 0; j < 4; j++) {
            r0 += acc[i][j][0] + acc[i][j][1];
            r1 += acc[i][j][2] + acc[i][j][3];
        }
        r0 += __shfl_xor_sync(0xffffffffu, r0, 1);
        r0 += __shfl_xor_sync(0xffffffffu, r0, 2);
        r1 += __shfl_xor_sync(0xffffffffu, r1, 1);
        r1 += __shfl_xor_sync(0xffffffffu, r1, 2);
        if ((lane & 3) == 0) {
            int rbase = warpM * 64 + i * 16 + (lane >> 2);
            atomicAdd(&rowsum_s[rbase], r0);
            atomicAdd(&rowsum_s[rbase + 8], r1);
        }
    }
    #pragma unroll
    for (int j = 0; j < 4; j++) {
        float c0 = 0.f, c1 = 0.f;
        #pragma unroll
        for (int i = 0; i < 4; i++) {
            c0 += acc[i][j][0] + acc[i][j][2];
            c1 += acc[i][j][1] + acc[i][j][3];
        }
        c0 += __shfl_xor_sync(0xffffffffu, c0, 4);
        c0 += __shfl_xor_sync(0xffffffffu, c0, 8);
        c0 += __shfl_xor_sync(0xffffffffu, c0, 16);
        c1 += __shfl_xor_sync(0xffffffffu, c1, 4);
        c1 += __shfl_xor_sync(0xffffffffu, c1, 8);
        c1 += __shfl_xor_sync(0xffffffffu, c1, 16);
        if (lane < 4) {
            int cbase = warpN * 32 + j * 8 + lane * 2;
            atomicAdd(&colsum_s[cbase], c0);
            atomicAdd(&colsum_s[cbase + 1], c1);
        }
    }

    __syncthreads();
    if (tid < BM) {
        atomicAdd(&g_rowsum[rowBase + tid], rowsum_s[tid]);
        atomicAdd(&g_colsum[colBase + tid], colsum_s[tid]);
    }
}

// ---------------- 5) two-stage finalize ----------------
__global__ void partial_kernel() {
    int tid = threadIdx.x;
    int row = blockIdx.x * 256 + tid;
    float a = log2f(g_rowsum[row]) + log2f(g_colsum[row]);
    float d = g_diag[row];
    #pragma unroll
    for (int o = 16; o; o >>= 1) {
        a += __shfl_xor_sync(0xffffffffu, a, o);
        d += __shfl_xor_sync(0xffffffffu, d, o);
    }
    __shared__ float sa[8], sd[8];
    if ((tid & 31) == 0) { sa[tid >> 5] = a; sd[tid >> 5] = d; }
    __syncthreads();
    if (tid == 0) {
        float ta = 0.f, td = 0.f;
        #pragma unroll
        for (int i = 0; i < 8; i++) { ta += sa[i]; td += sd[i]; }
        g_parta[blockIdx.x] = ta;
        g_partd[blockIdx.x] = td;
    }
}

__global__ void final_kernel(float* __restrict__ out) {
    int lane = threadIdx.x;
    float a = g_parta[lane], d = g_partd[lane];
    #pragma unroll
    for (int o = 16; o; o >>= 1) {
        a += __shfl_xor_sync(0xffffffffu, a, o);
        d += __shfl_xor_sync(0xffffffffu, d, o);
    }
    if (lane == 0)
        out[0] = LN2F * (0.5f * a / (float)NROWS - d / (float)NROWS);
}

// ---------------- launch ----------------
extern "C" void kernel_launch(void* const* d_in, const int* in_sizes, int n_in,
                              void* d_out, int out_size) {
    const float* im  = (const float*)d_in[0];
    const float* cap = (const float*)d_in[1];
    float* out = (float*)d_out;

    cudaFuncSetAttribute(gemm_kernel, cudaFuncAttributeMaxDynamicSharedMemorySize, DYN_BYTES);

    normalize_kernel<<<dim3(NROWS, 2), 256>>>(im, cap);
    zero_kernel<<<(NROWS + 255) / 256, 256>>>();
    diag_kernel<<<NROWS / 8, 256>>>();
    gemm_kernel<<<dim3(NROWS / BN, NROWS / BM), 256, DYN_BYTES>>>();
    partial_kernel<<<32, 256>>>();
    final_kernel<<<1, 32>>>(out);
}

// round 9
// speedup vs baseline: 1.0581x; 1.0581x over previous
#include <cuda_runtime.h>
#include <cuda_bf16.h>
#include <cstdint>

#define NROWS 8192
#define DIM   1024
#define SCALE_T 14.4269504088896341f   // (1/T)*log2(e)
#define LN2F 0.69314718055994531f

// ---------------- scratch ----------------
__device__ __nv_bfloat16 g_imn[(size_t)NROWS * DIM];   // normalized * SCALE_T
__device__ __nv_bfloat16 g_capn[(size_t)NROWS * DIM];  // normalized
__device__ float g_rowsum[NROWS];
__device__ float g_colsum[NROWS];
__device__ float g_diag[NROWS];                        // t_ii (exp2-domain logits)
__device__ float g_parta[32];
__device__ float g_partd[32];

// ---------------- helpers ----------------
__device__ __forceinline__ uint32_t smem_u32(const void* p) {
    uint32_t a;
    asm("{ .reg .u64 t; cvta.to.shared.u64 t, %1; cvt.u32.u64 %0, t; }" : "=r"(a) : "l"(p));
    return a;
}
__device__ __forceinline__ uint64_t gmem_u64(const void* p) {
    uint64_t a;
    asm("cvta.to.global.u64 %0, %1;" : "=l"(a) : "l"(p));
    return a;
}
#define SW128(o) ((o) ^ (((o) >> 3) & 0x70))

// ---------------- 1) normalize ----------------
__global__ void normalize_kernel(const float* __restrict__ im,
                                 const float* __restrict__ cap) {
    int row = blockIdx.x;
    const float* src = (blockIdx.y == 0) ? im : cap;
    __nv_bfloat16* dst = (blockIdx.y == 0) ? g_imn : g_capn;
    float cscale = (blockIdx.y == 0) ? SCALE_T : 1.0f;

    const float4* src4 = reinterpret_cast<const float4*>(src + (size_t)row * DIM);
    float4 v = src4[threadIdx.x];
    float ss = v.x * v.x + v.y * v.y + v.z * v.z + v.w * v.w;
    #pragma unroll
    for (int o = 16; o; o >>= 1) ss += __shfl_xor_sync(0xffffffffu, ss, o);
    __shared__ float wss[8];
    if ((threadIdx.x & 31) == 0) wss[threadIdx.x >> 5] = ss;
    __syncthreads();
    float total = 0.f;
    #pragma unroll
    for (int i = 0; i < 8; i++) total += wss[i];

    float inv = rsqrtf(total) * cscale;
    __nv_bfloat162* d2 = reinterpret_cast<__nv_bfloat162*>(dst + (size_t)row * DIM);
    d2[threadIdx.x * 2 + 0] = __floats2bfloat162_rn(v.x * inv, v.y * inv);
    d2[threadIdx.x * 2 + 1] = __floats2bfloat162_rn(v.z * inv, v.w * inv);
}

// ---------------- 2) zero ----------------
__global__ void zero_kernel() {
    int i = blockIdx.x * blockDim.x + threadIdx.x;
    if (i < NROWS) { g_rowsum[i] = 0.f; g_colsum[i] = 0.f; }
}

// ---------------- 3) diag: t_ii = dot(imn_scaled[i], capn[i]) ----------------
__global__ void diag_kernel() {
    int wid = threadIdx.x >> 5, lane = threadIdx.x & 31;
    int row = blockIdx.x * 8 + wid;
    const uint4* A = reinterpret_cast<const uint4*>(g_imn + (size_t)row * DIM);
    const uint4* B = reinterpret_cast<const uint4*>(g_capn + (size_t)row * DIM);
    float acc = 0.f;
    #pragma unroll
    for (int q = 0; q < 4; q++) {
        uint4 a = A[lane + 32 * q], b = B[lane + 32 * q];
        const __nv_bfloat162* pa = reinterpret_cast<const __nv_bfloat162*>(&a);
        const __nv_bfloat162* pb = reinterpret_cast<const __nv_bfloat162*>(&b);
        #pragma unroll
        for (int j = 0; j < 4; j++) {
            float2 fa = __bfloat1622float2(pa[j]);
            float2 fb = __bfloat1622float2(pb[j]);
            acc += fa.x * fb.x + fa.y * fb.y;
        }
    }
    #pragma unroll
    for (int o = 16; o; o >>= 1) acc += __shfl_xor_sync(0xffffffffu, acc, o);
    if (lane == 0) g_diag[row] = acc;
}

// ---------------- 4) bf16 mma.sync GEMM, 4 warps, 64x64 warp tiles ----------------
// CTA tile 128x128, BK=64, 3-stage cp.async. Warp grid 2x2, warp tile 64x64
// = 4 m-frags (m16) x 8 n-frags (n8).
#define BM 128
#define BN 128
#define STAGE_BYTES 32768                 // A 16KB + B 16KB
#define DYN_BYTES (3 * STAGE_BYTES + 1024)

extern __shared__ char dynsmem[];

__device__ __forceinline__ void issue_tile(uint32_t sStage, uint64_t gA, uint64_t gB,
                                           int c, int tid) {
    const uint32_t k0b = (uint32_t)c * 128;          // 128 B per BK chunk
    #pragma unroll
    for (int q = 0; q < 8; q++) {
        int chunk = tid + q * 128;
        int row = chunk >> 3, kc = chunk & 7;
        uint32_t soff = SW128(row * 128 + kc * 16);
        uint64_t goff = (uint64_t)row * (DIM * 2) + k0b + kc * 16;
        asm volatile("cp.async.cg.shared.global [%0], [%1], 16;"
                     :: "r"(sStage + soff), "l"(gA + goff) : "memory");
        asm volatile("cp.async.cg.shared.global [%0], [%1], 16;"
                     :: "r"(sStage + 16384 + soff), "l"(gB + goff) : "memory");
    }
}

__global__ void __launch_bounds__(128, 2) gemm_kernel() {
    const int tid = threadIdx.x, wid = tid >> 5, lane = tid & 31;
    const int warpM = wid >> 1;           // 0..1 -> 64-row slab
    const int warpN = wid & 1;            // 0..1 -> 64-col slab
    const int rowBase = blockIdx.y * BM;
    const int colBase = blockIdx.x * BN;

    __shared__ float rowsum_s[BM];
    __shared__ float colsum_s[BN];
    rowsum_s[tid] = 0.f;
    colsum_s[tid] = 0.f;

    uint32_t raw = smem_u32(dynsmem);
    uint32_t sbase = (raw + 1023u) & ~1023u;

    const uint64_t gA = gmem_u64(&g_imn[(size_t)rowBase * DIM]);
    const uint64_t gB = gmem_u64(&g_capn[(size_t)colBase * DIM]);

    issue_tile(sbase + 0 * STAGE_BYTES, gA, gB, 0, tid);
    asm volatile("cp.async.commit_group;" ::: "memory");
    issue_tile(sbase + 1 * STAGE_BYTES, gA, gB, 1, tid);
    asm volatile("cp.async.commit_group;" ::: "memory");

    float acc[4][8][4];
    #pragma unroll
    for (int i = 0; i < 4; i++)
        #pragma unroll
        for (int j = 0; j < 8; j++)
            #pragma unroll
            for (int r = 0; r < 4; r++) acc[i][j][r] = 0.f;

    // ldmatrix lane geometry
    const int laneRow = lane & 15;
    const uint32_t aXor = (uint32_t)((laneRow & 7) << 4);
    const uint32_t aHi  = (uint32_t)((lane >> 4) * 16);
    const int rowB0 = ((lane >> 4) & 1) * 8 + (lane & 7);
    const uint32_t bXor = (uint32_t)((lane & 7) << 4);
    const uint32_t bHi  = (uint32_t)(((lane >> 3) & 1) * 16);

    for (int c = 0; c < 16; c++) {
        asm volatile("cp.async.wait_group 1;" ::: "memory");
        __syncthreads();
        if (c + 2 < 16)
            issue_tile(sbase + ((c + 2) % 3) * STAGE_BYTES, gA, gB, c + 2, tid);
        asm volatile("cp.async.commit_group;" ::: "memory");

        const uint32_t sA = sbase + (c % 3) * STAGE_BYTES;
        const uint32_t sB = sA + 16384;

        #pragma unroll
        for (int kk = 0; kk < 4; kk++) {
            uint32_t a[4][4], b[4][4];
            #pragma unroll
            for (int i = 0; i < 4; i++) {
                uint32_t addr = sA + (uint32_t)(warpM * 64 + i * 16 + laneRow) * 128
                              + (((uint32_t)kk * 32 + aHi) ^ aXor);
                asm volatile("ldmatrix.sync.aligned.m8n8.x4.shared.b16 {%0,%1,%2,%3}, [%4];"
                             : "=r"(a[i][0]), "=r"(a[i][1]), "=r"(a[i][2]), "=r"(a[i][3])
                             : "r"(addr));
            }
            #pragma unroll
            for (int jb = 0; jb < 4; jb++) {
                uint32_t addr = sB + (uint32_t)(warpN * 64 + jb * 16 + rowB0) * 128
                              + (((uint32_t)kk * 32 + bHi) ^ bXor);
                asm volatile("ldmatrix.sync.aligned.m8n8.x4.shared.b16 {%0,%1,%2,%3}, [%4];"
                             : "=r"(b[jb][0]), "=r"(b[jb][1]), "=r"(b[jb][2]), "=r"(b[jb][3])
                             : "r"(addr));
            }
            #pragma unroll
            for (int i = 0; i < 4; i++) {
                #pragma unroll
                for (int j = 0; j < 8; j++) {
                    uint32_t b0 = b[j >> 1][(j & 1) * 2];
                    uint32_t b1 = b[j >> 1][(j & 1) * 2 + 1];
                    asm volatile(
                        "mma.sync.aligned.m16n8k16.row.col.f32.bf16.bf16.f32 "
                        "{%0,%1,%2,%3}, {%4,%5,%6,%7}, {%8,%9}, {%0,%1,%2,%3};"
                        : "+f"(acc[i][j][0]), "+f"(acc[i][j][1]),
                          "+f"(acc[i][j][2]), "+f"(acc[i][j][3])
                        : "r"(a[i][0]), "r"(a[i][1]), "r"(a[i][2]), "r"(a[i][3]),
                          "r"(b0), "r"(b1));
                }
            }
        }
    }

    // ---- epilogue: exp2 in place, register reductions ----
    #pragma unroll
    for (int i = 0; i < 4; i++)
        #pragma unroll
        for (int j = 0; j < 8; j++)
            #pragma unroll
            for (int r = 0; r < 4; r++)
                asm("ex2.approx.f32 %0, %0;" : "+f"(acc[i][j][r]));

    // row sums
    #pragma unroll
    for (int i = 0; i < 4; i++) {
        float r0 = 0.f, r1 = 0.f;
        #pragma unroll
        for (int j = 0; j < 8; j++) {
            r0 += acc[i][j][0] + acc[i][j][1];
            r1 += acc[i][j][2] + acc[i][j][3];
        }
        r0 += __shfl_xor_sync(0xffffffffu, r0, 1);
        r0 += __shfl_xor_sync(0xffffffffu, r0, 2);
        r1 += __shfl_xor_sync(0xffffffffu, r1, 1);
        r1 += __shfl_xor_sync(0xffffffffu, r1, 2);
        if ((lane & 3) == 0) {
            int rbase = warpM * 64 + i * 16 + (lane >> 2);
            atomicAdd(&rowsum_s[rbase], r0);
            atomicAdd(&rowsum_s[rbase + 8], r1);
        }
    }
    // col sums
    #pragma unroll
    for (int j = 0; j < 8; j++) {
        float c0 = 0.f, c1 = 0.f;
        #pragma unroll
        for (int i = 0; i < 4; i++) {
            c0 += acc[i][j][0] + acc[i][j][2];
            c1 += acc[i][j][1] + acc[i][j][3];
        }
        c0 += __shfl_xor_sync(0xffffffffu, c0, 4);
        c0 += __shfl_xor_sync(0xffffffffu, c0, 8);
        c0 += __shfl_xor_sync(0xffffffffu, c0, 16);
        c1 += __shfl_xor_sync(0xffffffffu, c1, 4);
        c1 += __shfl_xor_sync(0xffffffffu, c1, 8);
        c1 += __shfl_xor_sync(0xffffffffu, c1, 16);
        if (lane < 4) {
            int cbase = warpN * 64 + j * 8 + lane * 2;
            atomicAdd(&colsum_s[cbase], c0);
            atomicAdd(&colsum_s[cbase + 1], c1);
        }
    }

    __syncthreads();
    atomicAdd(&g_rowsum[rowBase + tid], rowsum_s[tid]);
    atomicAdd(&g_colsum[colBase + tid], colsum_s[tid]);
}

// ---------------- 5) two-stage finalize ----------------
__global__ void partial_kernel() {
    int tid = threadIdx.x;
    int row = blockIdx.x * 256 + tid;
    float a = log2f(g_rowsum[row]) + log2f(g_colsum[row]);
    float d = g_diag[row];
    #pragma unroll
    for (int o = 16; o; o >>= 1) {
        a += __shfl_xor_sync(0xffffffffu, a, o);
        d += __shfl_xor_sync(0xffffffffu, d, o);
    }
    __shared__ float sa[8], sd[8];
    if ((tid & 31) == 0) { sa[tid >> 5] = a; sd[tid >> 5] = d; }
    __syncthreads();
    if (tid == 0) {
        float ta = 0.f, td = 0.f;
        #pragma unroll
        for (int i = 0; i < 8; i++) { ta += sa[i]; td += sd[i]; }
        g_parta[blockIdx.x] = ta;
        g_partd[blockIdx.x] = td;
    }
}

__global__ void final_kernel(float* __restrict__ out) {
    int lane = threadIdx.x;
    float a = g_parta[lane], d = g_partd[lane];
    #pragma unroll
    for (int o = 16; o; o >>= 1) {
        a += __shfl_xor_sync(0xffffffffu, a, o);
        d += __shfl_xor_sync(0xffffffffu, d, o);
    }
    if (lane == 0)
        out[0] = LN2F * (0.5f * a / (float)NROWS - d / (float)NROWS);
}

// ---------------- launch ----------------
extern "C" void kernel_launch(void* const* d_in, const int* in_sizes, int n_in,
                              void* d_out, int out_size) {
    const float* im  = (const float*)d_in[0];
    const float* cap = (const float*)d_in[1];
    float* out = (float*)d_out;

    cudaFuncSetAttribute(gemm_kernel, cudaFuncAttributeMaxDynamicSharedMemorySize, DYN_BYTES);

    normalize_kernel<<<dim3(NROWS, 2), 256>>>(im, cap);
    zero_kernel<<<(NROWS + 255) / 256, 256>>>();
    diag_kernel<<<NROWS / 8, 256>>>();
    gemm_kernel<<<dim3(NROWS / BN, NROWS / BM), 128, DYN_BYTES>>>();
    partial_kernel<<<32, 256>>>();
    final_kernel<<<1, 32>>>(out);
}